// round 17
// baseline (speedup 1.0000x reference)
#include <cuda_runtime.h>

#define BATCH 64
#define N     4096
#define NX    128
#define NU    32
#define NY    32
#define L     64
#define NCHUNK (N / L)     // 64
#define MS    (NX * NX)    // 16384

#define Y_ELEMS ((size_t)BATCH * N * NY)

// Scratch (no cudaMalloc allowed)
__device__ float g_PA[6][MS];               // A^2, A^4, A^8, A^16, A^32, A^64
__device__ float g_M[64][NX * NU];          // M[m] = A^m * B   (128x32 each)
__device__ float g_WL[BATCH * NCHUNK * NX]; // chunk-local end contributions
__device__ float g_XS[BATCH * NCHUNK * NX]; // chunk start states x_{cL}
__device__ float g_V[(size_t)BATCH * N * NX]; // V[b][t] = B u_t

// ---------------------------------------------------------------------------
// 128x128 matrix square: out = in * in. grid=128 (row), block=128 (col).
// ---------------------------------------------------------------------------
__global__ void __launch_bounds__(NX) matsq(const float* __restrict__ in,
                                            float* __restrict__ out)
{
    __shared__ float row[NX];
    const int r = blockIdx.x, c = threadIdx.x;
    row[c] = in[r * NX + c];
    __syncthreads();
    float acc = 0.f;
#pragma unroll 16
    for (int j = 0; j < NX; j++) acc += row[j] * in[j * NX + c];
    out[r * NX + c] = acc;
}

// ---------------------------------------------------------------------------
// build_M: ONE launch for all M[m] = A^m B, m = 0..63. grid=64, block=128.
// ---------------------------------------------------------------------------
__global__ void __launch_bounds__(NX) build_M(
    const float* __restrict__ A,
    const float* __restrict__ B)
{
    __shared__ float cur[NX * NU];   // 16 KB
    const int m = blockIdx.x, r = threadIdx.x;

    for (int idx = r; idx < NX * NU; idx += NX) cur[idx] = B[idx];
    __syncthreads();

    for (int s = 0; s < 6; s++) {
        if ((m >> s) & 1) {
            const float* P = (s == 0) ? A : g_PA[s - 1];
            float a[NX];
            {
                const float4* p4 = (const float4*)(P + (size_t)r * NX);
#pragma unroll
                for (int j = 0; j < NX / 4; j++) {
                    float4 v = p4[j];
                    a[4 * j + 0] = v.x; a[4 * j + 1] = v.y;
                    a[4 * j + 2] = v.z; a[4 * j + 3] = v.w;
                }
            }
            float acc[NU];
#pragma unroll
            for (int v = 0; v < NU; v++) acc[v] = 0.f;
#pragma unroll 4
            for (int j = 0; j < NX; j++) {
                float pj = a[j];
#pragma unroll
                for (int v = 0; v < NU; v++) acc[v] += pj * cur[j * NU + v];
            }
            __syncthreads();
#pragma unroll
            for (int v = 0; v < NU; v++) cur[r * NU + v] = acc[v];
            __syncthreads();
        }
    }

    float* Mo = g_M[m];
    for (int idx = r; idx < NX * NU; idx += NX) Mo[idx] = cur[idx];
}

// ---------------------------------------------------------------------------
// V kernel v1 (measured best: 93us).
// ---------------------------------------------------------------------------
__global__ void __launch_bounds__(NX) v_kernel(
    const float* __restrict__ d,
    const float* __restrict__ B,
    float* __restrict__ V)
{
    __shared__ float us[32][NU];
    const int t0 = blockIdx.x * 32;
    const int b  = blockIdx.y;
    const int r  = threadIdx.x;

    {
        const float4* ug4 = (const float4*)(d + ((size_t)b * N + t0) * NU);
        float4* us4 = (float4*)&us[0][0];
#pragma unroll
        for (int q = 0; q < (32 * NU / 4) / NX; q++)
            us4[r + NX * q] = ug4[r + NX * q];
    }
    __syncthreads();

    float bb[NU];
    {
        const float4* b4 = (const float4*)(B + (size_t)r * NU);
#pragma unroll
        for (int q = 0; q < NU / 4; q++) {
            float4 v = b4[q];
            bb[4 * q + 0] = v.x; bb[4 * q + 1] = v.y;
            bb[4 * q + 2] = v.z; bb[4 * q + 3] = v.w;
        }
    }

    float* Vb = V + ((size_t)b * N + t0) * NX;
#pragma unroll 4
    for (int t = 0; t < 32; t++) {
        const float4* u4 = (const float4*)us[t];
        float a0 = 0.f, a1 = 0.f, a2 = 0.f, a3 = 0.f;
#pragma unroll
        for (int q = 0; q < NU / 4; q++) {
            float4 v = u4[q];
            a0 += bb[4 * q + 0] * v.x;
            a1 += bb[4 * q + 1] * v.y;
            a2 += bb[4 * q + 2] * v.z;
            a3 += bb[4 * q + 3] * v.w;
        }
        Vb[(size_t)t * NX + r] = (a0 + a1) + (a2 + a3);
    }
}

// ---------------------------------------------------------------------------
// GEMM for chunk-end contributions (unchanged).
// ---------------------------------------------------------------------------
__global__ void __launch_bounds__(NX) gemm_wl(
    const float* __restrict__ d,
    float* __restrict__ WL)
{
    __shared__ float us[16][128];

    const int c0 = blockIdx.x * 16;
    const int b  = blockIdx.y;
    const int r  = threadIdx.x;

    const float* ub = d + (size_t)b * N * NU;

    float acc[16];
#pragma unroll
    for (int cc = 0; cc < 16; cc++) acc[cc] = 0.f;

    for (int kt = 0; kt < 16; kt++) {
        __syncthreads();
        for (int idx = r; idx < 16 * 128; idx += 128) {
            int cc = idx >> 7, kk = idx & 127;
            us[cc][kk] = ub[(size_t)(c0 + cc) * (L * NU) + kt * 128 + kk];
        }
        __syncthreads();

#pragma unroll
        for (int jj = 0; jj < 4; jj++) {
            int j = kt * 4 + jj;
            const float4* mrow = (const float4*)(g_M[63 - j] + (size_t)r * NU);
            float m[NU];
#pragma unroll
            for (int q = 0; q < NU / 4; q++) {
                float4 w = mrow[q];
                m[4 * q + 0] = w.x; m[4 * q + 1] = w.y;
                m[4 * q + 2] = w.z; m[4 * q + 3] = w.w;
            }
#pragma unroll
            for (int v = 0; v < NU; v++) {
                float mv = m[v];
#pragma unroll
                for (int cc = 0; cc < 16; cc++)
                    acc[cc] += mv * us[cc][jj * 32 + v];
            }
        }
    }

#pragma unroll
    for (int cc = 0; cc < 16; cc++)
        WL[((size_t)b * NCHUNK + c0 + cc) * NX + r] = acc[cc];
}

// ---------------------------------------------------------------------------
// Pass 2: serial combine (unchanged).
// ---------------------------------------------------------------------------
__global__ void __launch_bounds__(NX) pass2_combine(
    const float* __restrict__ A64,
    const float* __restrict__ WL,
    float* __restrict__ XS)
{
    __shared__ float s[NX];
    const int b = blockIdx.x, i = threadIdx.x;

    float a[NX];
#pragma unroll
    for (int j = 0; j < NX; j++) a[j] = A64[i * NX + j];

    float* xsb = XS + (size_t)b * NCHUNK * NX;

    s[i] = 0.f;
    xsb[i] = 0.f;
    __syncthreads();

    for (int c = 0; c < NCHUNK - 1; c++) {
        const float4* s4 = (const float4*)s;
        float acc0 = 0.f, acc1 = 0.f, acc2 = 0.f, acc3 = 0.f;
#pragma unroll
        for (int j = 0; j < NX / 4; j++) {
            float4 v = s4[j];
            acc0 += a[4 * j + 0] * v.x;
            acc1 += a[4 * j + 1] * v.y;
            acc2 += a[4 * j + 2] * v.z;
            acc3 += a[4 * j + 3] * v.w;
        }
        float wl = WL[((size_t)b * NCHUNK + c) * NX + i];
        float ns = (acc0 + acc1) + (acc2 + acc3) + wl;
        __syncthreads();
        s[i] = ns;
        xsb[(size_t)(c + 1) * NX + i] = ns;
        __syncthreads();
    }
}

// ---------------------------------------------------------------------------
// Warp-specialized fused sweep + inline y.
// 192 threads: 0-127 = scan (exact R16 recurrence), 128-191 = y-warps
// (one channel x stream each, C row in registers, reading the live xs buffer).
// Both branches execute exactly one __syncthreads per step (64 total).
// ---------------------------------------------------------------------------
__global__ void __launch_bounds__(192, 2) pass4_fused(
    const float* __restrict__ V,
    const float* __restrict__ A,
    const float* __restrict__ XS,
    const float* __restrict__ d,
    const float* __restrict__ Cm,
    const float* __restrict__ Dm,
    float* __restrict__ xout,
    float* __restrict__ yout)
{
    __shared__ float  xs[2][2][NX];     // 4 KB  scan double buffer
    __shared__ float  ush[2][L][NU];    // 16 KB u for both streams, whole chunk
    __shared__ float4 Dsh[NU / 4][NY];  // 4 KB  D transposed

    const int c  = blockIdx.x;
    const int b0 = blockIdx.y;
    const int b1 = blockIdx.y + BATCH / 2;
    const int i  = threadIdx.x;

    // Stage u (both streams, 512 float4 each) and D (256 float4)
    {
        const float4* u0 = (const float4*)(d + ((size_t)b0 * N + (size_t)c * L) * NU);
        const float4* u1 = (const float4*)(d + ((size_t)b1 * N + (size_t)c * L) * NU);
        float4* s0 = (float4*)&ush[0][0][0];
        float4* s1 = (float4*)&ush[1][0][0];
        for (int idx = i; idx < 512; idx += 192) {
            s0[idx] = u0[idx];
            s1[idx] = u1[idx];
        }
        const float4* D4 = (const float4*)Dm;
        for (int f = i; f < 256; f += 192)
            Dsh[f & 7][f >> 3] = D4[f];
    }

    if (i < NX) {
        xs[0][0][i] = XS[((size_t)b0 * NCHUNK + c) * NX + i];
        xs[0][1][i] = XS[((size_t)b1 * NCHUNK + c) * NX + i];
        if (c == 0) {
            xout[(size_t)b0 * (N + 1) * NX + i] = 0.0f;
            xout[(size_t)b1 * (N + 1) * NX + i] = 0.0f;
        }
    }
    __syncthreads();

    if (i < NX) {
        // ---------------- scan branch (identical arithmetic to R16) --------
        float a[NX];
#pragma unroll
        for (int j = 0; j < NX; j++) a[j] = A[i * NX + j];

        const float* V0 = V + ((size_t)b0 * N + (size_t)c * L) * NX + i;
        const float* V1 = V + ((size_t)b1 * N + (size_t)c * L) * NX + i;
        float* x0 = xout + (size_t)b0 * (N + 1) * NX + (size_t)c * L * NX;
        float* x1 = xout + (size_t)b1 * (N + 1) * NX + (size_t)c * L * NX;

        float v00 = V0[0], v01 = V0[NX];
        float v10 = V1[0], v11 = V1[NX];

        int p = 0;
        for (int k = 0; k < L; k++) {
            const float4* xa  = (const float4*)xs[p][0];
            const float4* xbv = (const float4*)xs[p][1];
            float s00 = v00, s01 = 0.f, s02 = 0.f, s03 = 0.f;
            float s10 = v10, s11 = 0.f, s12 = 0.f, s13 = 0.f;
#pragma unroll
            for (int j = 0; j < NX / 4; j++) {
                float4 u0 = xa[j];
                float4 u1 = xbv[j];
                float aj0 = a[4 * j + 0], aj1 = a[4 * j + 1];
                float aj2 = a[4 * j + 2], aj3 = a[4 * j + 3];
                s00 += aj0 * u0.x;  s10 += aj0 * u1.x;
                s01 += aj1 * u0.y;  s11 += aj1 * u1.y;
                s02 += aj2 * u0.z;  s12 += aj2 * u1.z;
                s03 += aj3 * u0.w;  s13 += aj3 * u1.w;
            }
            float w0 = (s00 + s01) + (s02 + s03);
            float w1 = (s10 + s11) + (s12 + s13);

            v00 = v01;  v10 = v11;
            if (k + 2 < L) {
                v01 = V0[(size_t)(k + 2) * NX];
                v11 = V1[(size_t)(k + 2) * NX];
            }

            xs[p ^ 1][0][i] = w0;
            xs[p ^ 1][1][i] = w1;
            x0[(size_t)(k + 1) * NX + i] = w0;
            x1[(size_t)(k + 1) * NX + i] = w1;
            __syncthreads();
            p ^= 1;
        }
    } else {
        // ---------------- y branch: 64 threads, one (channel, stream) each -
        const int t = i - NX;          // 0..63
        const int o = t & 31;          // output channel
        const int s = t >> 5;          // stream 0/1

        float creg[NX];
        {
            const float4* c4 = (const float4*)(Cm + (size_t)o * NX);
#pragma unroll
            for (int j = 0; j < NX / 4; j++) {
                float4 v = c4[j];
                creg[4 * j + 0] = v.x; creg[4 * j + 1] = v.y;
                creg[4 * j + 2] = v.z; creg[4 * j + 3] = v.w;
            }
        }

        const int b = s ? b1 : b0;
        float* yb = yout + ((size_t)b * N + (size_t)c * L) * NY;

        int p = 0;
        for (int k = 0; k < L; k++) {
            const float4* xr = (const float4*)xs[p][s];   // x_{cL+k}
            const float4* ur = (const float4*)ush[s][k];
            float a0 = 0.f, a1 = 0.f, a2 = 0.f, a3 = 0.f;
#pragma unroll
            for (int j4 = 0; j4 < NX / 4; j4++) {
                float4 v = xr[j4];                        // broadcast read
                a0 += creg[4 * j4 + 0] * v.x;
                a1 += creg[4 * j4 + 1] * v.y;
                a2 += creg[4 * j4 + 2] * v.z;
                a3 += creg[4 * j4 + 3] * v.w;
            }
#pragma unroll
            for (int q = 0; q < NU / 4; q++) {
                float4 v  = ur[q];                        // broadcast read
                float4 dq = Dsh[q][o];
                a0 += dq.x * v.x;
                a1 += dq.y * v.y;
                a2 += dq.z * v.z;
                a3 += dq.w * v.w;
            }
            yb[(size_t)k * NY + o] = (a0 + a1) + (a2 + a3);
            __syncthreads();
            p ^= 1;
        }
    }
}

// ---------------------------------------------------------------------------
extern "C" void kernel_launch(void* const* d_in, const int* in_sizes, int n_in,
                              void* d_out, int out_size)
{
    const float* d = (const float*)d_in[0];
    const float* A = (const float*)d_in[1];
    const float* B = (const float*)d_in[2];
    const float* C = (const float*)d_in[3];
    const float* D = (const float*)d_in[4];

    float* y = (float*)d_out;
    float* x = (float*)d_out + Y_ELEMS;

    float* PA;  cudaGetSymbolAddress((void**)&PA, g_PA);
    float* WL;  cudaGetSymbolAddress((void**)&WL, g_WL);
    float* XS;  cudaGetSymbolAddress((void**)&XS, g_XS);
    float* V;   cudaGetSymbolAddress((void**)&V,  g_V);

    // #1-#3: A^2, A^4, A^8
    matsq<<<NX, NX>>>(A,           PA + 0 * MS);
    matsq<<<NX, NX>>>(PA + 0 * MS, PA + 1 * MS);
    matsq<<<NX, NX>>>(PA + 1 * MS, PA + 2 * MS);

    // #4 (ncu captures launch #4): V = B u
    {
        dim3 g(N / 32, BATCH);
        v_kernel<<<g, NX>>>(d, B, V);
    }

    // #5-#7: A^16, A^32, A^64
    matsq<<<NX, NX>>>(PA + 2 * MS, PA + 3 * MS);
    matsq<<<NX, NX>>>(PA + 3 * MS, PA + 4 * MS);
    matsq<<<NX, NX>>>(PA + 4 * MS, PA + 5 * MS);

    // #8: all M[m] = A^m B in one launch
    build_M<<<64, NX>>>(A, B);

    // #9: chunk-end contributions via GEMM
    {
        dim3 g(NCHUNK / 16, BATCH);
        gemm_wl<<<g, NX>>>(d, WL);
    }

    // #10: serial chunk combine -> start states
    pass2_combine<<<BATCH, NX>>>(PA + 5 * MS, WL, XS);

    // #11: warp-specialized fused sweep + inline y
    {
        dim3 g(NCHUNK, BATCH / 2);
        pass4_fused<<<g, 192>>>(V, A, XS, d, C, D, x, y);
    }
}